// round 2
// baseline (speedup 1.0000x reference)
#include <cuda_runtime.h>
#include <cuda_bf16.h>
#include <math.h>

// ParallelEncoderBlock: LN -> fused proj GEMM -> MHA (flash) -> gelu gate
//                       -> out = inputs + concat@w_attn + gated@w_ff
// B=2, S=2048, D=1024, H=16, d=64, FF=4096, NPROJ=11264. tf32 mma.sync.

#define ROWS_TOT   4096
#define MODEL_D    1024
#define NPROJ      11264
#define FF_D       4096
#define ATTN_D     1024

__device__ float g_units[ROWS_TOT * MODEL_D];
__device__ float g_proj[(size_t)ROWS_TOT * NPROJ];
__device__ float g_concat[ROWS_TOT * ATTN_D];
__device__ float g_gated[(size_t)ROWS_TOT * FF_D];

__device__ __forceinline__ unsigned f2tf32(float x) {
    unsigned r;
    asm("cvt.rna.tf32.f32 %0, %1;" : "=r"(r) : "f"(x));
    return r;
}

__device__ __forceinline__ void mma_tf32(float d[4],
                                         unsigned a0, unsigned a1, unsigned a2, unsigned a3,
                                         unsigned b0, unsigned b1) {
    asm volatile(
        "mma.sync.aligned.m16n8k8.row.col.f32.tf32.tf32.f32 "
        "{%0,%1,%2,%3}, {%4,%5,%6,%7}, {%8,%9}, {%0,%1,%2,%3};"
        : "+f"(d[0]), "+f"(d[1]), "+f"(d[2]), "+f"(d[3])
        : "r"(a0), "r"(a1), "r"(a2), "r"(a3), "r"(b0), "r"(b1));
}

// ---------------- LayerNorm: one block per row ----------------
__global__ void __launch_bounds__(256) ln_kernel(const float* __restrict__ x,
                                                 const float* __restrict__ w,
                                                 const float* __restrict__ b,
                                                 float* __restrict__ out) {
    const int row = blockIdx.x;
    const int t = threadIdx.x;
    float4 v = ((const float4*)(x + (size_t)row * MODEL_D))[t];
    float s  = v.x + v.y + v.z + v.w;
    float ss = v.x * v.x + v.y * v.y + v.z * v.z + v.w * v.w;
#pragma unroll
    for (int o = 16; o > 0; o >>= 1) {
        s  += __shfl_xor_sync(0xffffffffu, s, o);
        ss += __shfl_xor_sync(0xffffffffu, ss, o);
    }
    __shared__ float rs[8], rss[8];
    const int warp = t >> 5, lane = t & 31;
    if (lane == 0) { rs[warp] = s; rss[warp] = ss; }
    __syncthreads();
    float S = 0.f, SS = 0.f;
#pragma unroll
    for (int i = 0; i < 8; i++) { S += rs[i]; SS += rss[i]; }
    const float mu   = S * (1.0f / MODEL_D);
    const float var  = SS * (1.0f / MODEL_D) - mu * mu;
    const float rstd = rsqrtf(var + 1e-5f);
    const float4 wv = ((const float4*)w)[t];
    const float4 bv = ((const float4*)b)[t];
    float4 o4;
    o4.x = (v.x - mu) * rstd * wv.x + bv.x;
    o4.y = (v.y - mu) * rstd * wv.y + bv.y;
    o4.z = (v.z - mu) * rstd * wv.z + bv.z;
    o4.w = (v.w - mu) * rstd * wv.w + bv.w;
    ((float4*)(out + (size_t)row * MODEL_D))[t] = o4;
}

// ---------------- tf32 GEMM: C = A[M,K] @ B[K,N] (+addsrc) ----------------
// Tile 128x128, BK=16, 256 threads = 8 warps (4x2), each warp 32x64.
#define GS 136

__global__ void __launch_bounds__(256) gemm_tf32_kernel(
    const float* __restrict__ A, const float* __restrict__ Bm,
    float* __restrict__ C, const float* __restrict__ addsrc,
    int M, int N, int K) {
    __shared__ unsigned As[16 * GS];   // [k][m]
    __shared__ unsigned Bs[16 * GS];   // [k][n]

    const int tid  = threadIdx.x;
    const int lane = tid & 31;
    const int wid  = tid >> 5;
    const int g    = lane >> 2;
    const int tg   = lane & 3;
    const int wm   = wid & 3;
    const int wn   = wid >> 2;
    const int row0 = blockIdx.y * 128;
    const int col0 = blockIdx.x * 128;

    const int arow = tid >> 1, acol = (tid & 1) * 8;
    const int brow = tid >> 4, bcol = (tid & 15) * 8;

    float c[2][8][4];
#pragma unroll
    for (int mi = 0; mi < 2; mi++)
#pragma unroll
        for (int ni = 0; ni < 8; ni++)
#pragma unroll
            for (int q = 0; q < 4; q++) c[mi][ni][q] = 0.f;

    for (int k0 = 0; k0 < K; k0 += 16) {
        const float* ap = A + (size_t)(row0 + arow) * K + k0 + acol;
        float4 av0 = *(const float4*)ap;
        float4 av1 = *(const float4*)(ap + 4);
        const float* bp = Bm + (size_t)(k0 + brow) * N + col0 + bcol;
        float4 bv0 = *(const float4*)bp;
        float4 bv1 = *(const float4*)(bp + 4);

        As[(acol + 0) * GS + arow] = f2tf32(av0.x);
        As[(acol + 1) * GS + arow] = f2tf32(av0.y);
        As[(acol + 2) * GS + arow] = f2tf32(av0.z);
        As[(acol + 3) * GS + arow] = f2tf32(av0.w);
        As[(acol + 4) * GS + arow] = f2tf32(av1.x);
        As[(acol + 5) * GS + arow] = f2tf32(av1.y);
        As[(acol + 6) * GS + arow] = f2tf32(av1.z);
        As[(acol + 7) * GS + arow] = f2tf32(av1.w);

        Bs[brow * GS + bcol + 0] = f2tf32(bv0.x);
        Bs[brow * GS + bcol + 1] = f2tf32(bv0.y);
        Bs[brow * GS + bcol + 2] = f2tf32(bv0.z);
        Bs[brow * GS + bcol + 3] = f2tf32(bv0.w);
        Bs[brow * GS + bcol + 4] = f2tf32(bv1.x);
        Bs[brow * GS + bcol + 5] = f2tf32(bv1.y);
        Bs[brow * GS + bcol + 6] = f2tf32(bv1.z);
        Bs[brow * GS + bcol + 7] = f2tf32(bv1.w);
        __syncthreads();

#pragma unroll
        for (int kk = 0; kk < 16; kk += 8) {
            unsigned a[2][4];
#pragma unroll
            for (int mi = 0; mi < 2; mi++) {
                const int mr = wm * 32 + mi * 16;
                a[mi][0] = As[(kk + tg) * GS + mr + g];
                a[mi][1] = As[(kk + tg) * GS + mr + g + 8];
                a[mi][2] = As[(kk + tg + 4) * GS + mr + g];
                a[mi][3] = As[(kk + tg + 4) * GS + mr + g + 8];
            }
#pragma unroll
            for (int ni = 0; ni < 8; ni++) {
                const int nc = wn * 64 + ni * 8 + g;
                unsigned b0 = Bs[(kk + tg) * GS + nc];
                unsigned b1 = Bs[(kk + tg + 4) * GS + nc];
                mma_tf32(c[0][ni], a[0][0], a[0][1], a[0][2], a[0][3], b0, b1);
                mma_tf32(c[1][ni], a[1][0], a[1][1], a[1][2], a[1][3], b0, b1);
            }
        }
        __syncthreads();
    }

#pragma unroll
    for (int mi = 0; mi < 2; mi++) {
        const int r0 = row0 + wm * 32 + mi * 16 + g;
#pragma unroll
        for (int ni = 0; ni < 8; ni++) {
            const int cc = col0 + wn * 64 + ni * 8 + 2 * tg;
            const size_t i0 = (size_t)r0 * N + cc;
            const size_t i1 = (size_t)(r0 + 8) * N + cc;
            float2 v0 = make_float2(c[mi][ni][0], c[mi][ni][1]);
            float2 v1 = make_float2(c[mi][ni][2], c[mi][ni][3]);
            if (addsrc) {
                float2 s0 = *(const float2*)&addsrc[i0];
                float2 s1 = *(const float2*)&addsrc[i1];
                v0.x += s0.x; v0.y += s0.y;
                v1.x += s1.x; v1.y += s1.y;
            }
            *(float2*)&C[i0] = v0;
            *(float2*)&C[i1] = v1;
        }
    }
}

// ---------------- Flash attention (tf32 mma) ----------------
// block = (qtile of 64 rows, head, batch); 256 threads = 8 warps (4x2).
#define ATS 68

__global__ void __launch_bounds__(256) attn_kernel(const float* __restrict__ proj,
                                                   float* __restrict__ concat) {
    extern __shared__ unsigned sm_u[];
    unsigned* Qs   = sm_u;                      // [64][ATS] tf32, pre-scaled
    unsigned* Ks   = Qs + 64 * ATS;             // [64][ATS]
    unsigned* VsT  = Ks + 64 * ATS;             // [d][j]
    float*    Ss   = (float*)(VsT + 64 * ATS);  // [64][ATS]; becomes P
    float* alpha_s = Ss + 64 * ATS;             // [64]
    float* l_s     = alpha_s + 64;              // [64]

    const int tid  = threadIdx.x;
    const int lane = tid & 31;
    const int wid  = tid >> 5;
    const int g    = lane >> 2;
    const int tg   = lane & 3;
    const int wm   = wid & 3;
    const int wn   = wid >> 2;
    const int tx   = tid & 15, ty = tid >> 4;

    const int qt = blockIdx.x, h = blockIdx.y, b = blockIdx.z;
    const int qbase = b * 2048 + qt * 64;
    const float* qg = proj + (size_t)qbase * NPROJ + h * 64;
    const float* kg = proj + (size_t)(b * 2048) * NPROJ + 1024 + h * 64;
    const float* vg = kg + 1024;

    {   // load Q, scaled by 1/sqrt(64)=0.125
        const int i  = tid >> 2;
        const int d0 = (tid & 3) * 16;
        const float* src = qg + (size_t)i * NPROJ + d0;
#pragma unroll
        for (int tt = 0; tt < 16; tt += 4) {
            float4 v = *(const float4*)(src + tt);
            Qs[i * ATS + d0 + tt + 0] = f2tf32(v.x * 0.125f);
            Qs[i * ATS + d0 + tt + 1] = f2tf32(v.y * 0.125f);
            Qs[i * ATS + d0 + tt + 2] = f2tf32(v.z * 0.125f);
            Qs[i * ATS + d0 + tt + 3] = f2tf32(v.w * 0.125f);
        }
    }

    float m_old[4], lsum[4], o[4][4];
#pragma unroll
    for (int i = 0; i < 4; i++) {
        m_old[i] = -1e30f; lsum[i] = 0.f;
#pragma unroll
        for (int q = 0; q < 4; q++) o[i][q] = 0.f;
    }
    __syncthreads();

    for (int kt = 0; kt < 32; kt++) {
        {   // load K row-major, V transposed
            const int j  = tid >> 2;
            const int d0 = (tid & 3) * 16;
            const float* ks = kg + (size_t)(kt * 64 + j) * NPROJ + d0;
            const float* vs = vg + (size_t)(kt * 64 + j) * NPROJ + d0;
#pragma unroll
            for (int tt = 0; tt < 16; tt += 4) {
                float4 kv = *(const float4*)(ks + tt);
                Ks[j * ATS + d0 + tt + 0] = f2tf32(kv.x);
                Ks[j * ATS + d0 + tt + 1] = f2tf32(kv.y);
                Ks[j * ATS + d0 + tt + 2] = f2tf32(kv.z);
                Ks[j * ATS + d0 + tt + 3] = f2tf32(kv.w);
                float4 vv = *(const float4*)(vs + tt);
                VsT[(d0 + tt + 0) * ATS + j] = f2tf32(vv.x);
                VsT[(d0 + tt + 1) * ATS + j] = f2tf32(vv.y);
                VsT[(d0 + tt + 2) * ATS + j] = f2tf32(vv.z);
                VsT[(d0 + tt + 3) * ATS + j] = f2tf32(vv.w);
            }
        }
        __syncthreads();

        // S = Q @ K^T (per-warp 16x32)
        float sfr[4][4];
#pragma unroll
        for (int ni = 0; ni < 4; ni++)
#pragma unroll
            for (int q = 0; q < 4; q++) sfr[ni][q] = 0.f;
#pragma unroll
        for (int kk = 0; kk < 64; kk += 8) {
            const int mr = wm * 16;
            unsigned a0 = Qs[(mr + g) * ATS + kk + tg];
            unsigned a1 = Qs[(mr + g + 8) * ATS + kk + tg];
            unsigned a2 = Qs[(mr + g) * ATS + kk + tg + 4];
            unsigned a3 = Qs[(mr + g + 8) * ATS + kk + tg + 4];
#pragma unroll
            for (int ni = 0; ni < 4; ni++) {
                const int n0 = wn * 32 + ni * 8 + g;
                unsigned b0 = Ks[n0 * ATS + kk + tg];
                unsigned b1 = Ks[n0 * ATS + kk + tg + 4];
                mma_tf32(sfr[ni], a0, a1, a2, a3, b0, b1);
            }
        }
#pragma unroll
        for (int ni = 0; ni < 4; ni++) {
            const int col = wn * 32 + ni * 8 + 2 * tg;
            const int r0  = wm * 16 + g;
            *(float2*)&Ss[r0 * ATS + col]       = make_float2(sfr[ni][0], sfr[ni][1]);
            *(float2*)&Ss[(r0 + 8) * ATS + col] = make_float2(sfr[ni][2], sfr[ni][3]);
        }
        __syncthreads();

        // SIMT online softmax: thread (ty,tx) owns rows ty*4+ii, cols tx*4..
        unsigned* Ps = (unsigned*)Ss;
#pragma unroll
        for (int ii = 0; ii < 4; ii++) {
            const int r = ty * 4 + ii;
            float s0 = Ss[r * ATS + tx * 4 + 0];
            float s1 = Ss[r * ATS + tx * 4 + 1];
            float s2 = Ss[r * ATS + tx * 4 + 2];
            float s3 = Ss[r * ATS + tx * 4 + 3];
            float mx = fmaxf(fmaxf(s0, s1), fmaxf(s2, s3));
#pragma unroll
            for (int off = 1; off < 16; off <<= 1)
                mx = fmaxf(mx, __shfl_xor_sync(0xffffffffu, mx, off));
            const float mnew = fmaxf(m_old[ii], mx);
            float p0 = __expf(s0 - mnew);
            float p1 = __expf(s1 - mnew);
            float p2 = __expf(s2 - mnew);
            float p3 = __expf(s3 - mnew);
            float rsum = p0 + p1 + p2 + p3;
#pragma unroll
            for (int off = 1; off < 16; off <<= 1)
                rsum += __shfl_xor_sync(0xffffffffu, rsum, off);
            const float alpha = __expf(m_old[ii] - mnew);
            lsum[ii] = lsum[ii] * alpha + rsum;
            m_old[ii] = mnew;
            if (tx == 0) alpha_s[r] = alpha;
            Ps[r * ATS + tx * 4 + 0] = f2tf32(p0);
            Ps[r * ATS + tx * 4 + 1] = f2tf32(p1);
            Ps[r * ATS + tx * 4 + 2] = f2tf32(p2);
            Ps[r * ATS + tx * 4 + 3] = f2tf32(p3);
        }
        __syncthreads();

        // O = O*alpha + P @ V
        {
            const float alpha0 = alpha_s[wm * 16 + g];
            const float alpha1 = alpha_s[wm * 16 + g + 8];
#pragma unroll
            for (int ni = 0; ni < 4; ni++) {
                o[ni][0] *= alpha0; o[ni][1] *= alpha0;
                o[ni][2] *= alpha1; o[ni][3] *= alpha1;
            }
#pragma unroll
            for (int kk = 0; kk < 64; kk += 8) {
                const int mr = wm * 16;
                unsigned a0 = Ps[(mr + g) * ATS + kk + tg];
                unsigned a1 = Ps[(mr + g + 8) * ATS + kk + tg];
                unsigned a2 = Ps[(mr + g) * ATS + kk + tg + 4];
                unsigned a3 = Ps[(mr + g + 8) * ATS + kk + tg + 4];
#pragma unroll
                for (int ni = 0; ni < 4; ni++) {
                    const int n0 = wn * 32 + ni * 8 + g;
                    unsigned b0 = VsT[n0 * ATS + kk + tg];
                    unsigned b1 = VsT[n0 * ATS + kk + tg + 4];
                    mma_tf32(o[ni], a0, a1, a2, a3, b0, b1);
                }
            }
        }
        __syncthreads();
    }

    if (tx == 0) {
#pragma unroll
        for (int ii = 0; ii < 4; ii++) l_s[ty * 4 + ii] = lsum[ii];
    }
    __syncthreads();
    {
        const float inv0 = 1.0f / l_s[wm * 16 + g];
        const float inv1 = 1.0f / l_s[wm * 16 + g + 8];
#pragma unroll
        for (int ni = 0; ni < 4; ni++) {
            const int col = h * 64 + wn * 32 + ni * 8 + 2 * tg;
            const int r   = qbase + wm * 16 + g;
            *(float2*)&concat[(size_t)r * ATTN_D + col] =
                make_float2(o[ni][0] * inv0, o[ni][1] * inv0);
            *(float2*)&concat[(size_t)(r + 8) * ATTN_D + col] =
                make_float2(o[ni][2] * inv1, o[ni][3] * inv1);
        }
    }
}

// ---------------- GELU gating ----------------
__device__ __forceinline__ float gelu_tanh(float x) {
    const float x3 = x * x * x;
    return 0.5f * x * (1.0f + tanhf(0.7978845608028654f * (x + 0.044715f * x3)));
}

__global__ void __launch_bounds__(256) gelu_kernel(const float* __restrict__ proj,
                                                   float* __restrict__ gated) {
    const int idx = blockIdx.x * 256 + threadIdx.x;   // float4 over [4096][1024]
    const int m  = idx >> 10;
    const int c4 = idx & 1023;
    const float* base = proj + (size_t)m * NPROJ;
    float4 f  = *(const float4*)(base + 3072 + c4 * 4);
    float4 gg = *(const float4*)(base + 7168 + c4 * 4);
    float4 r;
    r.x = f.x * gelu_tanh(gg.x);
    r.y = f.y * gelu_tanh(gg.y);
    r.z = f.z * gelu_tanh(gg.z);
    r.w = f.w * gelu_tanh(gg.w);
    *(float4*)(gated + (size_t)m * FF_D + c4 * 4) = r;
}

// ---------------- Launch ----------------
extern "C" void kernel_launch(void* const* d_in, const int* in_sizes, int n_in,
                              void* d_out, int out_size) {
    const float* x      = (const float*)d_in[0];
    const float* lnw    = (const float*)d_in[1];
    const float* lnb    = (const float*)d_in[2];
    const float* w_in   = (const float*)d_in[3];
    const float* w_attn = (const float*)d_in[4];
    const float* w_ff   = (const float*)d_in[5];
    float* out = (float*)d_out;

    float *units, *proj, *concat, *gated;
    cudaGetSymbolAddress((void**)&units,  g_units);
    cudaGetSymbolAddress((void**)&proj,   g_proj);
    cudaGetSymbolAddress((void**)&concat, g_concat);
    cudaGetSymbolAddress((void**)&gated,  g_gated);

    const int attn_smem = (3 * 64 * ATS) * 4 + (64 * ATS) * 4 + 2 * 64 * 4;
    cudaFuncSetAttribute(attn_kernel,
                         cudaFuncAttributeMaxDynamicSharedMemorySize, attn_smem);

    // 1) LayerNorm
    ln_kernel<<<ROWS_TOT, 256>>>(x, lnw, lnb, units);

    // 2) Fused projection: [4096,1024] @ [1024,11264]
    gemm_tf32_kernel<<<dim3(NPROJ / 128, ROWS_TOT / 128), 256>>>(
        units, w_in, proj, nullptr, ROWS_TOT, NPROJ, MODEL_D);

    // 3) Flash attention -> concat [4096,1024]
    attn_kernel<<<dim3(32, 16, 2), 256, attn_smem>>>(proj, concat);

    // 4) GELU gating -> gated [4096,4096]
    gelu_kernel<<<(ROWS_TOT * FF_D / 4) / 256, 256>>>(proj, gated);

    // 5) out = x + concat @ w_attn
    gemm_tf32_kernel<<<dim3(MODEL_D / 128, ROWS_TOT / 128), 256>>>(
        concat, w_attn, out, x, ROWS_TOT, MODEL_D, ATTN_D);

    // 6) out += gated @ w_ff
    gemm_tf32_kernel<<<dim3(MODEL_D / 128, ROWS_TOT / 128), 256>>>(
        gated, w_ff, out, out, ROWS_TOT, MODEL_D, FF_D);
}

// round 4
// speedup vs baseline: 1.8819x; 1.8819x over previous
#include <cuda_runtime.h>
#include <cuda_bf16.h>
#include <cstdint>
#include <math.h>

// ParallelEncoderBlock: LN -> bf16 mma.sync proj GEMM -> flash MHA (tf32 mma.sync)
// -> gelu gate -> fused output GEMM (bf16 mma.sync) with f32 residual.
// NOTE: harness ptxas targets sm_103 (no 'a') => tcgen05 unavailable; use mma.sync.

#define ROWS_TOT   4096
#define MODEL_D    1024
#define NPROJ      11264
#define FF_D       4096
#define ATTN_D     1024
#define KOUT       5120

// ---------------- scratch ----------------
__device__ __nv_bfloat16 g_units[ROWS_TOT * MODEL_D];
__device__ __nv_bfloat16 g_proj[(size_t)ROWS_TOT * NPROJ];
__device__ __nv_bfloat16 g_concat[ROWS_TOT * ATTN_D];
__device__ __nv_bfloat16 g_gated[(size_t)ROWS_TOT * FF_D];
__device__ __nv_bfloat16 g_wT_in[(size_t)NPROJ * MODEL_D];   // [n][k]
__device__ __nv_bfloat16 g_wT_out[(size_t)MODEL_D * KOUT];   // [n][attn_k | ff_k]

// ---------------- helpers ----------------
__device__ __forceinline__ uint32_t smem_u32(const void* p) {
    uint32_t a;
    asm("{ .reg .u64 t; cvta.to.shared.u64 t, %1; cvt.u32.u64 %0, t; }" : "=r"(a) : "l"(p));
    return a;
}
__device__ __forceinline__ void cp16(uint32_t dst, const void* src) {
    asm volatile("cp.async.cg.shared.global [%0], [%1], 16;" :: "r"(dst), "l"(src));
}
#define CP_COMMIT() asm volatile("cp.async.commit_group;" ::: "memory")
#define CP_WAIT1()  asm volatile("cp.async.wait_group 1;" ::: "memory")
#define CP_WAIT0()  asm volatile("cp.async.wait_group 0;" ::: "memory")

__device__ __forceinline__ void ldm_x4(uint32_t* r, uint32_t addr) {
    asm volatile("ldmatrix.sync.aligned.m8n8.x4.shared.b16 {%0,%1,%2,%3}, [%4];"
        : "=r"(r[0]), "=r"(r[1]), "=r"(r[2]), "=r"(r[3]) : "r"(addr));
}
__device__ __forceinline__ void mma_bf16(float c[4], const uint32_t a[4], const uint32_t b[2]) {
    asm volatile(
        "mma.sync.aligned.m16n8k16.row.col.f32.bf16.bf16.f32 "
        "{%0,%1,%2,%3},{%4,%5,%6,%7},{%8,%9},{%0,%1,%2,%3};"
        : "+f"(c[0]), "+f"(c[1]), "+f"(c[2]), "+f"(c[3])
        : "r"(a[0]), "r"(a[1]), "r"(a[2]), "r"(a[3]), "r"(b[0]), "r"(b[1]));
}
__device__ __forceinline__ unsigned f2tf32(float x) {
    unsigned r;
    asm("cvt.rna.tf32.f32 %0, %1;" : "=r"(r) : "f"(x));
    return r;
}
__device__ __forceinline__ void mma_tf32(float d[4],
                                         unsigned a0, unsigned a1, unsigned a2, unsigned a3,
                                         unsigned b0, unsigned b1) {
    asm volatile(
        "mma.sync.aligned.m16n8k8.row.col.f32.tf32.tf32.f32 "
        "{%0,%1,%2,%3}, {%4,%5,%6,%7}, {%8,%9}, {%0,%1,%2,%3};"
        : "+f"(d[0]), "+f"(d[1]), "+f"(d[2]), "+f"(d[3])
        : "r"(a0), "r"(a1), "r"(a2), "r"(a3), "r"(b0), "r"(b1));
}
__device__ __forceinline__ void unpack8(uint4 u, float* f) {
    const __nv_bfloat162* h = (const __nv_bfloat162*)&u;
#pragma unroll
    for (int j = 0; j < 4; j++) {
        float2 v = __bfloat1622float2(h[j]);
        f[2 * j] = v.x; f[2 * j + 1] = v.y;
    }
}

// ---------------- weight transpose f32[K][N] -> bf16 out[n][koff+k] ----------------
__global__ void __launch_bounds__(256) transpose_to_bf16(
    const float* __restrict__ in, __nv_bfloat16* __restrict__ out,
    int K, int N, int out_ld, int koff) {
    __shared__ float t[32][33];
    const int n0 = blockIdx.x * 32, k0 = blockIdx.y * 32;
    const int tx = threadIdx.x, ty = threadIdx.y;
#pragma unroll
    for (int i = 0; i < 4; i++)
        t[ty + 8 * i][tx] = in[(size_t)(k0 + ty + 8 * i) * N + n0 + tx];
    __syncthreads();
#pragma unroll
    for (int i = 0; i < 4; i++)
        out[(size_t)(n0 + ty + 8 * i) * out_ld + koff + k0 + tx] =
            __float2bfloat16(t[tx][ty + 8 * i]);
}

// ---------------- LayerNorm -> bf16 ----------------
__global__ void __launch_bounds__(256) ln_kernel(const float* __restrict__ x,
                                                 const float* __restrict__ w,
                                                 const float* __restrict__ b,
                                                 __nv_bfloat16* __restrict__ out) {
    const int row = blockIdx.x;
    const int t = threadIdx.x;
    float4 v = ((const float4*)(x + (size_t)row * MODEL_D))[t];
    float s  = v.x + v.y + v.z + v.w;
    float ss = v.x * v.x + v.y * v.y + v.z * v.z + v.w * v.w;
#pragma unroll
    for (int o = 16; o > 0; o >>= 1) {
        s  += __shfl_xor_sync(0xffffffffu, s, o);
        ss += __shfl_xor_sync(0xffffffffu, ss, o);
    }
    __shared__ float rs[8], rss[8];
    const int warp = t >> 5, lane = t & 31;
    if (lane == 0) { rs[warp] = s; rss[warp] = ss; }
    __syncthreads();
    float S = 0.f, SS = 0.f;
#pragma unroll
    for (int i = 0; i < 8; i++) { S += rs[i]; SS += rss[i]; }
    const float mu   = S * (1.0f / MODEL_D);
    const float var  = SS * (1.0f / MODEL_D) - mu * mu;
    const float rstd = rsqrtf(var + 1e-5f);
    const float4 wv = ((const float4*)w)[t];
    const float4 bv = ((const float4*)b)[t];
    __nv_bfloat162 h0 = __float22bfloat162_rn(
        make_float2((v.x - mu) * rstd * wv.x + bv.x, (v.y - mu) * rstd * wv.y + bv.y));
    __nv_bfloat162 h1 = __float22bfloat162_rn(
        make_float2((v.z - mu) * rstd * wv.z + bv.z, (v.w - mu) * rstd * wv.w + bv.w));
    uint2 u = make_uint2(*(uint32_t*)&h0, *(uint32_t*)&h1);
    ((uint2*)(out + (size_t)row * MODEL_D))[t] = u;
}

// ---------------- bf16 mma.sync GEMM, 3-stage cp.async pipeline ----------------
// C[M, Ntot] = [A0 | A1] @ BT^T. Tiles 128x128, BK=32. BT is [Ntot][Ktot] bf16.
// smem per stage: A 128x40 bf16 (10240B) + B 128x40 bf16; 3 stages.
#define BK   32
#define AST  40
#define STAGE_A 10240
#define STAGE_B 10240
#define STAGES 3
#define GSMEM_TOT (STAGES * (STAGE_A + STAGE_B))

template <bool OUT_BF16>
__global__ void __launch_bounds__(256, 2) gemm_bf16(
    const __nv_bfloat16* __restrict__ A0, const __nv_bfloat16* __restrict__ A1,
    int c_switch, int lda0, int lda1,
    const __nv_bfloat16* __restrict__ BT, int ldb,
    void* __restrict__ Cout, int ldc,
    const float* __restrict__ addsrc, int n_chunks) {
    extern __shared__ char sm[];
    const uint32_t sA = smem_u32(sm);
    const uint32_t sB = sA + STAGES * STAGE_A;

    const int tid  = threadIdx.x;
    const int lane = tid & 31;
    const int wid  = tid >> 5;
    const int g    = lane >> 2;
    const int tg   = lane & 3;
    const int wm   = wid & 3;     // 32-row slice
    const int wn   = wid >> 2;    // 64-col slice
    const int row0 = blockIdx.y * 128;
    const int col0 = blockIdx.x * 128;

    // cp.async assignments: 2 A-chunks + 2 B-chunks per thread, 16B each
    const int ar0 = tid >> 2, as0 = tid & 3;           // A chunk tid
    const int ar1 = (tid + 256) >> 2, as1 = as0;       // A chunk tid+256
    const int br0 = ar0, bs0 = as0, br1 = ar1, bs1 = as1;

    auto issue_stage = [&](int c, int buf) {
        const __nv_bfloat16* Ap; int lda, koff;
        if (c < c_switch) { Ap = A0; lda = lda0; koff = c * BK; }
        else              { Ap = A1; lda = lda1; koff = (c - c_switch) * BK; }
        const uint32_t abase = sA + buf * STAGE_A;
        const uint32_t bbase = sB + buf * STAGE_B;
        cp16(abase + (ar0 * AST + as0 * 8) * 2, Ap + (size_t)(row0 + ar0) * lda + koff + as0 * 8);
        cp16(abase + (ar1 * AST + as1 * 8) * 2, Ap + (size_t)(row0 + ar1) * lda + koff + as1 * 8);
        const int kb = c * BK;
        cp16(bbase + (br0 * AST + bs0 * 8) * 2, BT + (size_t)(col0 + br0) * ldb + kb + bs0 * 8);
        cp16(bbase + (br1 * AST + bs1 * 8) * 2, BT + (size_t)(col0 + br1) * ldb + kb + bs1 * 8);
        CP_COMMIT();
    };

    float c[2][8][4];
#pragma unroll
    for (int mi = 0; mi < 2; mi++)
#pragma unroll
        for (int ni = 0; ni < 8; ni++)
#pragma unroll
            for (int q = 0; q < 4; q++) c[mi][ni][q] = 0.f;

    // ldmatrix lane addressing
    const int a_row = lane & 15, a_kh = lane >> 4;
    const int b_n   = (lane & 7) + ((lane >> 4) << 3);
    const int b_kh  = (lane >> 3) & 1;

    issue_stage(0, 0);
    if (n_chunks > 1) issue_stage(1, 1);
    int fetch = (n_chunks > 1) ? 2 : 1;

    for (int cc = 0; cc < n_chunks; cc++) {
        if (fetch > cc + 1) CP_WAIT1(); else CP_WAIT0();
        __syncthreads();
        if (fetch < n_chunks) { issue_stage(fetch, fetch % STAGES); fetch++; }

        const uint32_t abase = sA + (cc % STAGES) * STAGE_A;
        const uint32_t bbase = sB + (cc % STAGES) * STAGE_B;
#pragma unroll
        for (int ks = 0; ks < 2; ks++) {
            uint32_t af[2][4];
#pragma unroll
            for (int mi = 0; mi < 2; mi++)
                ldm_x4(af[mi], abase +
                       ((wm * 32 + mi * 16 + a_row) * AST + ks * 16 + a_kh * 8) * 2);
            uint32_t bf[8][2];
#pragma unroll
            for (int bp = 0; bp < 4; bp++) {
                uint32_t r[4];
                ldm_x4(r, bbase +
                       ((wn * 64 + bp * 16 + b_n) * AST + ks * 16 + b_kh * 8) * 2);
                bf[2 * bp][0] = r[0]; bf[2 * bp][1] = r[1];
                bf[2 * bp + 1][0] = r[2]; bf[2 * bp + 1][1] = r[3];
            }
#pragma unroll
            for (int mi = 0; mi < 2; mi++)
#pragma unroll
                for (int ni = 0; ni < 8; ni++)
                    mma_bf16(c[mi][ni], af[mi], bf[ni]);
        }
        __syncthreads();
    }

    // epilogue
#pragma unroll
    for (int mi = 0; mi < 2; mi++) {
        const int r0 = row0 + wm * 32 + mi * 16 + g;
#pragma unroll
        for (int ni = 0; ni < 8; ni++) {
            const int ccol = col0 + wn * 64 + ni * 8 + 2 * tg;
            const size_t i0 = (size_t)r0 * ldc + ccol;
            const size_t i1 = (size_t)(r0 + 8) * ldc + ccol;
            if (OUT_BF16) {
                __nv_bfloat16* Cb = (__nv_bfloat16*)Cout;
                *(__nv_bfloat162*)&Cb[i0] =
                    __float22bfloat162_rn(make_float2(c[mi][ni][0], c[mi][ni][1]));
                *(__nv_bfloat162*)&Cb[i1] =
                    __float22bfloat162_rn(make_float2(c[mi][ni][2], c[mi][ni][3]));
            } else {
                float* Cf = (float*)Cout;
                float2 v0 = make_float2(c[mi][ni][0], c[mi][ni][1]);
                float2 v1 = make_float2(c[mi][ni][2], c[mi][ni][3]);
                if (addsrc) {
                    float2 s0 = *(const float2*)&addsrc[i0];
                    float2 s1 = *(const float2*)&addsrc[i1];
                    v0.x += s0.x; v0.y += s0.y;
                    v1.x += s1.x; v1.y += s1.y;
                }
                *(float2*)&Cf[i0] = v0;
                *(float2*)&Cf[i1] = v1;
            }
        }
    }
}

// ---------------- Flash attention (tf32 mma.sync), bf16 I/O ----------------
#define ATS 68

__global__ void __launch_bounds__(256) attn_kernel(const __nv_bfloat16* __restrict__ proj,
                                                   __nv_bfloat16* __restrict__ concat) {
    extern __shared__ unsigned sm_u[];
    unsigned* Qs   = sm_u;
    unsigned* Ks   = Qs + 64 * ATS;
    unsigned* VsT  = Ks + 64 * ATS;
    float*    Ss   = (float*)(VsT + 64 * ATS);
    float* alpha_s = Ss + 64 * ATS;
    float* l_s     = alpha_s + 64;

    const int tid  = threadIdx.x;
    const int lane = tid & 31;
    const int wid  = tid >> 5;
    const int g    = lane >> 2;
    const int tg   = lane & 3;
    const int wm   = wid & 3;
    const int wn   = wid >> 2;
    const int tx   = tid & 15, ty = tid >> 4;

    const int qt = blockIdx.x, h = blockIdx.y, b = blockIdx.z;
    const int qbase = b * 2048 + qt * 64;
    const __nv_bfloat16* qg = proj + (size_t)qbase * NPROJ + h * 64;
    const __nv_bfloat16* kg = proj + (size_t)(b * 2048) * NPROJ + 1024 + h * 64;
    const __nv_bfloat16* vg = kg + 1024;

    {   // Q, pre-scaled by 0.125
        const int i  = tid >> 2;
        const int d0 = (tid & 3) * 16;
        const __nv_bfloat16* src = qg + (size_t)i * NPROJ + d0;
        float f[16];
        unpack8(*(const uint4*)src, f);
        unpack8(*(const uint4*)(src + 8), f + 8);
#pragma unroll
        for (int t = 0; t < 16; t++) Qs[i * ATS + d0 + t] = f2tf32(f[t] * 0.125f);
    }

    float m_old[4], lsum[4], o[4][4];
#pragma unroll
    for (int i = 0; i < 4; i++) {
        m_old[i] = -1e30f; lsum[i] = 0.f;
#pragma unroll
        for (int q = 0; q < 4; q++) o[i][q] = 0.f;
    }
    __syncthreads();

    for (int kt = 0; kt < 32; kt++) {
        {
            const int j  = tid >> 2;
            const int d0 = (tid & 3) * 16;
            const __nv_bfloat16* ks = kg + (size_t)(kt * 64 + j) * NPROJ + d0;
            const __nv_bfloat16* vs = vg + (size_t)(kt * 64 + j) * NPROJ + d0;
            float fk[16], fv[16];
            unpack8(*(const uint4*)ks, fk);
            unpack8(*(const uint4*)(ks + 8), fk + 8);
            unpack8(*(const uint4*)vs, fv);
            unpack8(*(const uint4*)(vs + 8), fv + 8);
#pragma unroll
            for (int t = 0; t < 16; t++) {
                Ks[j * ATS + d0 + t] = f2tf32(fk[t]);
                VsT[(d0 + t) * ATS + j] = f2tf32(fv[t]);
            }
        }
        __syncthreads();

        float sfr[4][4];
#pragma unroll
        for (int ni = 0; ni < 4; ni++)
#pragma unroll
            for (int q = 0; q < 4; q++) sfr[ni][q] = 0.f;
#pragma unroll
        for (int kk = 0; kk < 64; kk += 8) {
            const int mr = wm * 16;
            unsigned a0 = Qs[(mr + g) * ATS + kk + tg];
            unsigned a1 = Qs[(mr + g + 8) * ATS + kk + tg];
            unsigned a2 = Qs[(mr + g) * ATS + kk + tg + 4];
            unsigned a3 = Qs[(mr + g + 8) * ATS + kk + tg + 4];
#pragma unroll
            for (int ni = 0; ni < 4; ni++) {
                const int n0 = wn * 32 + ni * 8 + g;
                unsigned b0 = Ks[n0 * ATS + kk + tg];
                unsigned b1 = Ks[n0 * ATS + kk + tg + 4];
                mma_tf32(sfr[ni], a0, a1, a2, a3, b0, b1);
            }
        }
#pragma unroll
        for (int ni = 0; ni < 4; ni++) {
            const int col = wn * 32 + ni * 8 + 2 * tg;
            const int r0  = wm * 16 + g;
            *(float2*)&Ss[r0 * ATS + col]       = make_float2(sfr[ni][0], sfr[ni][1]);
            *(float2*)&Ss[(r0 + 8) * ATS + col] = make_float2(sfr[ni][2], sfr[ni][3]);
        }
        __syncthreads();

        unsigned* Ps = (unsigned*)Ss;
#pragma unroll
        for (int ii = 0; ii < 4; ii++) {
            const int r = ty * 4 + ii;
            float s0 = Ss[r * ATS + tx * 4 + 0];
            float s1 = Ss[r * ATS + tx * 4 + 1];
            float s2 = Ss[r * ATS + tx * 4 + 2];
            float s3 = Ss[r * ATS + tx * 4 + 3];
            float mx = fmaxf(fmaxf(s0, s1), fmaxf(s2, s3));
#pragma unroll
            for (int off = 1; off < 16; off <<= 1)
                mx = fmaxf(mx, __shfl_xor_sync(0xffffffffu, mx, off));
            const float mnew = fmaxf(m_old[ii], mx);
            float p0 = __expf(s0 - mnew);
            float p1 = __expf(s1 - mnew);
            float p2 = __expf(s2 - mnew);
            float p3 = __expf(s3 - mnew);
            float rsum = p0 + p1 + p2 + p3;
#pragma unroll
            for (int off = 1; off < 16; off <<= 1)
                rsum += __shfl_xor_sync(0xffffffffu, rsum, off);
            const float alpha = __expf(m_old[ii] - mnew);
            lsum[ii] = lsum[ii] * alpha + rsum;
            m_old[ii] = mnew;
            if (tx == 0) alpha_s[r] = alpha;
            Ps[r * ATS + tx * 4 + 0] = f2tf32(p0);
            Ps[r * ATS + tx * 4 + 1] = f2tf32(p1);
            Ps[r * ATS + tx * 4 + 2] = f2tf32(p2);
            Ps[r * ATS + tx * 4 + 3] = f2tf32(p3);
        }
        __syncthreads();

        {
            const float alpha0 = alpha_s[wm * 16 + g];
            const float alpha1 = alpha_s[wm * 16 + g + 8];
#pragma unroll
            for (int ni = 0; ni < 4; ni++) {
                o[ni][0] *= alpha0; o[ni][1] *= alpha0;
                o[ni][2] *= alpha1; o[ni][3] *= alpha1;
            }
#pragma unroll
            for (int kk = 0; kk < 64; kk += 8) {
                const int mr = wm * 16;
                unsigned a0 = Ps[(mr + g) * ATS + kk + tg];
                unsigned a1 = Ps[(mr + g + 8) * ATS + kk + tg];
                unsigned a2 = Ps[(mr + g) * ATS + kk + tg + 4];
                unsigned a3 = Ps[(mr + g + 8) * ATS + kk + tg + 4];
#pragma unroll
                for (int ni = 0; ni < 4; ni++) {
                    const int n0 = wn * 32 + ni * 8 + g;
                    unsigned b0 = VsT[n0 * ATS + kk + tg];
                    unsigned b1 = VsT[n0 * ATS + kk + tg + 4];
                    mma_tf32(o[ni], a0, a1, a2, a3, b0, b1);
                }
            }
        }
        __syncthreads();
    }

    if (tx == 0) {
#pragma unroll
        for (int ii = 0; ii < 4; ii++) l_s[ty * 4 + ii] = lsum[ii];
    }
    __syncthreads();
    {
        const float inv0 = 1.0f / l_s[wm * 16 + g];
        const float inv1 = 1.0f / l_s[wm * 16 + g + 8];
#pragma unroll
        for (int ni = 0; ni < 4; ni++) {
            const int col = h * 64 + wn * 32 + ni * 8 + 2 * tg;
            const int r   = qbase + wm * 16 + g;
            __nv_bfloat162 h0 = __float22bfloat162_rn(make_float2(o[ni][0] * inv0, o[ni][1] * inv0));
            __nv_bfloat162 h1 = __float22bfloat162_rn(make_float2(o[ni][2] * inv1, o[ni][3] * inv1));
            *(__nv_bfloat162*)&concat[(size_t)r * ATTN_D + col] = h0;
            *(__nv_bfloat162*)&concat[(size_t)(r + 8) * ATTN_D + col] = h1;
        }
    }
}

// ---------------- GELU gating (bf16) ----------------
__device__ __forceinline__ float gelu_tanh(float x) {
    const float x3 = x * x * x;
    return 0.5f * x * (1.0f + tanhf(0.7978845608028654f * (x + 0.044715f * x3)));
}

__global__ void __launch_bounds__(256) gelu_kernel(const __nv_bfloat16* __restrict__ proj,
                                                   __nv_bfloat16* __restrict__ gated) {
    const int idx = blockIdx.x * 256 + threadIdx.x;
    const int m  = idx >> 9;
    const int c8 = idx & 511;
    const __nv_bfloat16* base = proj + (size_t)m * NPROJ;
    float f[8], g[8];
    unpack8(*(const uint4*)(base + 3072 + c8 * 8), f);
    unpack8(*(const uint4*)(base + 7168 + c8 * 8), g);
    __nv_bfloat162 o[4];
#pragma unroll
    for (int j = 0; j < 4; j++)
        o[j] = __float22bfloat162_rn(make_float2(f[2 * j] * gelu_tanh(g[2 * j]),
                                                 f[2 * j + 1] * gelu_tanh(g[2 * j + 1])));
    *(uint4*)(gated + (size_t)m * FF_D + c8 * 8) = *(uint4*)o;
}

// ---------------- Launch ----------------
extern "C" void kernel_launch(void* const* d_in, const int* in_sizes, int n_in,
                              void* d_out, int out_size) {
    const float* x      = (const float*)d_in[0];
    const float* lnw    = (const float*)d_in[1];
    const float* lnb    = (const float*)d_in[2];
    const float* w_in   = (const float*)d_in[3];
    const float* w_attn = (const float*)d_in[4];
    const float* w_ff   = (const float*)d_in[5];
    float* out = (float*)d_out;

    __nv_bfloat16 *units, *proj, *concat, *gated, *wT_in, *wT_out;
    cudaGetSymbolAddress((void**)&units,  g_units);
    cudaGetSymbolAddress((void**)&proj,   g_proj);
    cudaGetSymbolAddress((void**)&concat, g_concat);
    cudaGetSymbolAddress((void**)&gated,  g_gated);
    cudaGetSymbolAddress((void**)&wT_in,  g_wT_in);
    cudaGetSymbolAddress((void**)&wT_out, g_wT_out);

    const int attn_smem = (3 * 64 * ATS) * 4 + (64 * ATS) * 4 + 2 * 64 * 4;
    cudaFuncSetAttribute(attn_kernel, cudaFuncAttributeMaxDynamicSharedMemorySize, attn_smem);
    cudaFuncSetAttribute(gemm_bf16<true>,  cudaFuncAttributeMaxDynamicSharedMemorySize, GSMEM_TOT);
    cudaFuncSetAttribute(gemm_bf16<false>, cudaFuncAttributeMaxDynamicSharedMemorySize, GSMEM_TOT);

    // 0) weight prep (bf16 transposes)
    transpose_to_bf16<<<dim3(NPROJ / 32, MODEL_D / 32), dim3(32, 8)>>>(
        w_in, wT_in, MODEL_D, NPROJ, MODEL_D, 0);
    transpose_to_bf16<<<dim3(MODEL_D / 32, ATTN_D / 32), dim3(32, 8)>>>(
        w_attn, wT_out, ATTN_D, MODEL_D, KOUT, 0);
    transpose_to_bf16<<<dim3(MODEL_D / 32, FF_D / 32), dim3(32, 8)>>>(
        w_ff, wT_out, FF_D, MODEL_D, KOUT, 1024);

    // 1) LayerNorm -> bf16
    ln_kernel<<<ROWS_TOT, 256>>>(x, lnw, lnb, units);

    // 2) proj = units @ w_in  (bf16 out), M=4096 N=11264 K=1024
    gemm_bf16<true><<<dim3(NPROJ / 128, ROWS_TOT / 128), 256, GSMEM_TOT>>>(
        units, units, 32, MODEL_D, MODEL_D, wT_in, MODEL_D,
        proj, NPROJ, nullptr, 32);

    // 3) attention -> concat (bf16)
    attn_kernel<<<dim3(32, 16, 2), 256, attn_smem>>>(proj, concat);

    // 4) gelu gating -> gated (bf16)
    gelu_kernel<<<(ROWS_TOT * FF_D / 8) / 256, 256>>>(proj, gated);

    // 5) out = x + concat @ w_attn + gated @ w_ff  (fused K=5120)
    gemm_bf16<false><<<dim3(MODEL_D / 128, ROWS_TOT / 128), 256, GSMEM_TOT>>>(
        concat, gated, 32, ATTN_D, FF_D, wT_out, KOUT,
        out, MODEL_D, x, 160);
}

// round 5
// speedup vs baseline: 2.8395x; 1.5088x over previous
#include <cuda_runtime.h>
#include <cuda_bf16.h>
#include <cstdint>
#include <math.h>

// ParallelEncoderBlock: LN -> bf16 mma.sync proj GEMM -> FA2-style bf16 MHA
// -> gelu gate -> fused output GEMM (bf16 mma.sync) with f32 residual.
// Harness ptxas targets sm_103 (no 'a') => no tcgen05; mma.sync/ldmatrix/cp.async only.

#define ROWS_TOT   4096
#define MODEL_D    1024
#define NPROJ      11264
#define FF_D       4096
#define ATTN_D     1024
#define KOUT       5120

// ---------------- scratch ----------------
__device__ __nv_bfloat16 g_units[ROWS_TOT * MODEL_D];
__device__ __nv_bfloat16 g_proj[(size_t)ROWS_TOT * NPROJ];
__device__ __nv_bfloat16 g_concat[ROWS_TOT * ATTN_D];
__device__ __nv_bfloat16 g_gated[(size_t)ROWS_TOT * FF_D];
__device__ __nv_bfloat16 g_wT_in[(size_t)NPROJ * MODEL_D];   // [n][k]
__device__ __nv_bfloat16 g_wT_out[(size_t)MODEL_D * KOUT];   // [n][attn_k | ff_k]

// ---------------- helpers ----------------
__device__ __forceinline__ uint32_t smem_u32(const void* p) {
    uint32_t a;
    asm("{ .reg .u64 t; cvta.to.shared.u64 t, %1; cvt.u32.u64 %0, t; }" : "=r"(a) : "l"(p));
    return a;
}
__device__ __forceinline__ void cp16(uint32_t dst, const void* src) {
    asm volatile("cp.async.cg.shared.global [%0], [%1], 16;" :: "r"(dst), "l"(src));
}
#define CP_COMMIT() asm volatile("cp.async.commit_group;" ::: "memory")
#define CP_WAIT1()  asm volatile("cp.async.wait_group 1;" ::: "memory")
#define CP_WAIT0()  asm volatile("cp.async.wait_group 0;" ::: "memory")

__device__ __forceinline__ void ldm_x4(uint32_t* r, uint32_t addr) {
    asm volatile("ldmatrix.sync.aligned.m8n8.x4.shared.b16 {%0,%1,%2,%3}, [%4];"
        : "=r"(r[0]), "=r"(r[1]), "=r"(r[2]), "=r"(r[3]) : "r"(addr));
}
__device__ __forceinline__ void ldm_x4_t(uint32_t* r, uint32_t addr) {
    asm volatile("ldmatrix.sync.aligned.m8n8.x4.trans.shared.b16 {%0,%1,%2,%3}, [%4];"
        : "=r"(r[0]), "=r"(r[1]), "=r"(r[2]), "=r"(r[3]) : "r"(addr));
}
__device__ __forceinline__ void mma_bf16(float c[4], const uint32_t a[4], const uint32_t b[2]) {
    asm volatile(
        "mma.sync.aligned.m16n8k16.row.col.f32.bf16.bf16.f32 "
        "{%0,%1,%2,%3},{%4,%5,%6,%7},{%8,%9},{%0,%1,%2,%3};"
        : "+f"(c[0]), "+f"(c[1]), "+f"(c[2]), "+f"(c[3])
        : "r"(a[0]), "r"(a[1]), "r"(a[2]), "r"(a[3]), "r"(b[0]), "r"(b[1]));
}
__device__ __forceinline__ uint32_t packbf(float x, float y) {
    __nv_bfloat162 h = __float22bfloat162_rn(make_float2(x, y));
    return *(uint32_t*)&h;
}
__device__ __forceinline__ void unpack8(uint4 u, float* f) {
    const __nv_bfloat162* h = (const __nv_bfloat162*)&u;
#pragma unroll
    for (int j = 0; j < 4; j++) {
        float2 v = __bfloat1622float2(h[j]);
        f[2 * j] = v.x; f[2 * j + 1] = v.y;
    }
}

// ---------------- weight transpose f32[K][N] -> bf16 out[n][koff+k] ----------------
__global__ void __launch_bounds__(256) transpose_to_bf16(
    const float* __restrict__ in, __nv_bfloat16* __restrict__ out,
    int K, int N, int out_ld, int koff) {
    __shared__ float t[32][33];
    const int n0 = blockIdx.x * 32, k0 = blockIdx.y * 32;
    const int tx = threadIdx.x, ty = threadIdx.y;
#pragma unroll
    for (int i = 0; i < 4; i++)
        t[ty + 8 * i][tx] = in[(size_t)(k0 + ty + 8 * i) * N + n0 + tx];
    __syncthreads();
#pragma unroll
    for (int i = 0; i < 4; i++)
        out[(size_t)(n0 + ty + 8 * i) * out_ld + koff + k0 + tx] =
            __float2bfloat16(t[tx][ty + 8 * i]);
}

// ---------------- LayerNorm -> bf16 ----------------
__global__ void __launch_bounds__(256) ln_kernel(const float* __restrict__ x,
                                                 const float* __restrict__ w,
                                                 const float* __restrict__ b,
                                                 __nv_bfloat16* __restrict__ out) {
    const int row = blockIdx.x;
    const int t = threadIdx.x;
    float4 v = ((const float4*)(x + (size_t)row * MODEL_D))[t];
    float s  = v.x + v.y + v.z + v.w;
    float ss = v.x * v.x + v.y * v.y + v.z * v.z + v.w * v.w;
#pragma unroll
    for (int o = 16; o > 0; o >>= 1) {
        s  += __shfl_xor_sync(0xffffffffu, s, o);
        ss += __shfl_xor_sync(0xffffffffu, ss, o);
    }
    __shared__ float rs[8], rss[8];
    const int warp = t >> 5, lane = t & 31;
    if (lane == 0) { rs[warp] = s; rss[warp] = ss; }
    __syncthreads();
    float S = 0.f, SS = 0.f;
#pragma unroll
    for (int i = 0; i < 8; i++) { S += rs[i]; SS += rss[i]; }
    const float mu   = S * (1.0f / MODEL_D);
    const float var  = SS * (1.0f / MODEL_D) - mu * mu;
    const float rstd = rsqrtf(var + 1e-5f);
    const float4 wv = ((const float4*)w)[t];
    const float4 bv = ((const float4*)b)[t];
    __nv_bfloat162 h0 = __float22bfloat162_rn(
        make_float2((v.x - mu) * rstd * wv.x + bv.x, (v.y - mu) * rstd * wv.y + bv.y));
    __nv_bfloat162 h1 = __float22bfloat162_rn(
        make_float2((v.z - mu) * rstd * wv.z + bv.z, (v.w - mu) * rstd * wv.w + bv.w));
    uint2 u = make_uint2(*(uint32_t*)&h0, *(uint32_t*)&h1);
    ((uint2*)(out + (size_t)row * MODEL_D))[t] = u;
}

// ---------------- bf16 mma.sync GEMM, 3-stage cp.async pipeline ----------------
#define BK   32
#define AST  40
#define STAGE_A 10240
#define STAGE_B 10240
#define STAGES 3
#define GSMEM_TOT (STAGES * (STAGE_A + STAGE_B))

template <bool OUT_BF16>
__global__ void __launch_bounds__(256, 2) gemm_bf16(
    const __nv_bfloat16* __restrict__ A0, const __nv_bfloat16* __restrict__ A1,
    int c_switch, int lda0, int lda1,
    const __nv_bfloat16* __restrict__ BT, int ldb,
    void* __restrict__ Cout, int ldc,
    const float* __restrict__ addsrc, int n_chunks) {
    extern __shared__ char sm[];
    const uint32_t sA = smem_u32(sm);
    const uint32_t sB = sA + STAGES * STAGE_A;

    const int tid  = threadIdx.x;
    const int lane = tid & 31;
    const int wid  = tid >> 5;
    const int g    = lane >> 2;
    const int tg   = lane & 3;
    const int wm   = wid & 3;
    const int wn   = wid >> 2;
    const int row0 = blockIdx.y * 128;
    const int col0 = blockIdx.x * 128;

    const int ar0 = tid >> 2, as0 = tid & 3;
    const int ar1 = (tid + 256) >> 2, as1 = as0;

    auto issue_stage = [&](int c, int buf) {
        const __nv_bfloat16* Ap; int lda, koff;
        if (c < c_switch) { Ap = A0; lda = lda0; koff = c * BK; }
        else              { Ap = A1; lda = lda1; koff = (c - c_switch) * BK; }
        const uint32_t abase = sA + buf * STAGE_A;
        const uint32_t bbase = sB + buf * STAGE_B;
        cp16(abase + (ar0 * AST + as0 * 8) * 2, Ap + (size_t)(row0 + ar0) * lda + koff + as0 * 8);
        cp16(abase + (ar1 * AST + as1 * 8) * 2, Ap + (size_t)(row0 + ar1) * lda + koff + as1 * 8);
        const int kb = c * BK;
        cp16(bbase + (ar0 * AST + as0 * 8) * 2, BT + (size_t)(col0 + ar0) * ldb + kb + as0 * 8);
        cp16(bbase + (ar1 * AST + as1 * 8) * 2, BT + (size_t)(col0 + ar1) * ldb + kb + as1 * 8);
        CP_COMMIT();
    };

    float c[2][8][4];
#pragma unroll
    for (int mi = 0; mi < 2; mi++)
#pragma unroll
        for (int ni = 0; ni < 8; ni++)
#pragma unroll
            for (int q = 0; q < 4; q++) c[mi][ni][q] = 0.f;

    const int a_row = lane & 15, a_kh = lane >> 4;
    const int b_n   = (lane & 7) + ((lane >> 4) << 3);
    const int b_kh  = (lane >> 3) & 1;

    issue_stage(0, 0);
    if (n_chunks > 1) issue_stage(1, 1);
    int fetch = (n_chunks > 1) ? 2 : 1;

    for (int cc = 0; cc < n_chunks; cc++) {
        if (fetch > cc + 1) CP_WAIT1(); else CP_WAIT0();
        __syncthreads();
        if (fetch < n_chunks) { issue_stage(fetch, fetch % STAGES); fetch++; }

        const uint32_t abase = sA + (cc % STAGES) * STAGE_A;
        const uint32_t bbase = sB + (cc % STAGES) * STAGE_B;
#pragma unroll
        for (int ks = 0; ks < 2; ks++) {
            uint32_t af[2][4];
#pragma unroll
            for (int mi = 0; mi < 2; mi++)
                ldm_x4(af[mi], abase +
                       ((wm * 32 + mi * 16 + a_row) * AST + ks * 16 + a_kh * 8) * 2);
            uint32_t bf[8][2];
#pragma unroll
            for (int bp = 0; bp < 4; bp++) {
                uint32_t r[4];
                ldm_x4(r, bbase +
                       ((wn * 64 + bp * 16 + b_n) * AST + ks * 16 + b_kh * 8) * 2);
                bf[2 * bp][0] = r[0]; bf[2 * bp][1] = r[1];
                bf[2 * bp + 1][0] = r[2]; bf[2 * bp + 1][1] = r[3];
            }
#pragma unroll
            for (int mi = 0; mi < 2; mi++)
#pragma unroll
                for (int ni = 0; ni < 8; ni++)
                    mma_bf16(c[mi][ni], af[mi], bf[ni]);
        }
        __syncthreads();
    }

#pragma unroll
    for (int mi = 0; mi < 2; mi++) {
        const int r0 = row0 + wm * 32 + mi * 16 + g;
#pragma unroll
        for (int ni = 0; ni < 8; ni++) {
            const int ccol = col0 + wn * 64 + ni * 8 + 2 * tg;
            const size_t i0 = (size_t)r0 * ldc + ccol;
            const size_t i1 = (size_t)(r0 + 8) * ldc + ccol;
            if (OUT_BF16) {
                __nv_bfloat16* Cb = (__nv_bfloat16*)Cout;
                *(uint32_t*)&Cb[i0] = packbf(c[mi][ni][0], c[mi][ni][1]);
                *(uint32_t*)&Cb[i1] = packbf(c[mi][ni][2], c[mi][ni][3]);
            } else {
                float* Cf = (float*)Cout;
                float2 v0 = make_float2(c[mi][ni][0], c[mi][ni][1]);
                float2 v1 = make_float2(c[mi][ni][2], c[mi][ni][3]);
                if (addsrc) {
                    float2 s0 = *(const float2*)&addsrc[i0];
                    float2 s1 = *(const float2*)&addsrc[i1];
                    v0.x += s0.x; v0.y += s0.y;
                    v1.x += s1.x; v1.y += s1.y;
                }
                *(float2*)&Cf[i0] = v0;
                *(float2*)&Cf[i1] = v1;
            }
        }
    }
}

// ---------------- FA2 attention (bf16 mma.sync, register P) ----------------
// block = (qtile 128 rows, head, batch), 256 thr = 8 warps x 16 rows.
// smem: Q [128][72], K/V 3-stage [64][72] each.
#define KTS 72
#define QBYTES (128 * KTS * 2)
#define KVSTG  (64 * KTS * 2)
#define ASMEM_TOT (QBYTES + 3 * 2 * KVSTG)
#define EXPC 0.18033688011112042f   // 0.125 * log2(e)

__global__ void __launch_bounds__(256) attn_kernel(const __nv_bfloat16* __restrict__ proj,
                                                   __nv_bfloat16* __restrict__ concat) {
    extern __shared__ char asm_[];
    const uint32_t sQ = smem_u32(asm_);
    const int tid  = threadIdx.x;
    const int lane = tid & 31;
    const int w    = tid >> 5;
    const int g    = lane >> 2;
    const int tg   = lane & 3;

    const int qt = blockIdx.x, h = blockIdx.y, b = blockIdx.z;
    const int qbase = b * 2048 + qt * 128;
    const __nv_bfloat16* qg = proj + (size_t)qbase * NPROJ + h * 64;
    const __nv_bfloat16* kg = proj + (size_t)(b * 2048) * NPROJ + 1024 + h * 64;
    const __nv_bfloat16* vg = kg + 1024;

    const int lrow = tid >> 3, lch = tid & 7;   // cp.async: rows of 8x16B

    auto sK = [&](int s) { return sQ + QBYTES + s * 2 * KVSTG; };
    auto sV = [&](int s) { return sQ + QBYTES + s * 2 * KVSTG + KVSTG; };

    // Q load (in async group 0)
#pragma unroll
    for (int i = 0; i < 4; i++) {
        const int r = i * 32 + lrow;
        cp16(sQ + (r * KTS + lch * 8) * 2, qg + (size_t)r * NPROJ + lch * 8);
    }
    auto loadKV = [&](int kt, int s) {
#pragma unroll
        for (int i = 0; i < 2; i++) {
            const int r = i * 32 + lrow;
            cp16(sK(s) + (r * KTS + lch * 8) * 2, kg + (size_t)(kt * 64 + r) * NPROJ + lch * 8);
            cp16(sV(s) + (r * KTS + lch * 8) * 2, vg + (size_t)(kt * 64 + r) * NPROJ + lch * 8);
        }
        CP_COMMIT();
    };

    loadKV(0, 0);
    loadKV(1, 1);
    int fetch = 2;

    uint32_t aq[4][4];
    float o[8][4];
    float m_lo = -1e30f, m_hi = -1e30f, l_lo = 0.f, l_hi = 0.f;
#pragma unroll
    for (int nd = 0; nd < 8; nd++)
#pragma unroll
        for (int q = 0; q < 4; q++) o[nd][q] = 0.f;

    const int a_row = lane & 15, a_kh = lane >> 4;
    // K b-frag addressing (per pair p, kstep ks)
    const int k_nt = (lane >> 4) & 1, k_kh = (lane >> 3) & 1, k_j = lane & 7;
    // V b-frag addressing (trans)
    const int v_dt = (lane >> 4) & 1, v_jh = (lane >> 3) & 1, v_j = lane & 7;

    for (int kt = 0; kt < 32; kt++) {
        if (fetch > kt + 1) CP_WAIT1(); else CP_WAIT0();
        __syncthreads();
        if (kt == 0) {
#pragma unroll
            for (int ks = 0; ks < 4; ks++)
                ldm_x4(aq[ks], sQ + ((w * 16 + a_row) * KTS + ks * 16 + a_kh * 8) * 2);
        }
        if (fetch < 32) { loadKV(fetch, fetch % STAGES); fetch++; }

        const uint32_t kb = sK(kt % STAGES);
        const uint32_t vb = sV(kt % STAGES);

        // ---- S = Q @ K^T : c[8][4] ----
        float c[8][4];
#pragma unroll
        for (int ni = 0; ni < 8; ni++)
#pragma unroll
            for (int q = 0; q < 4; q++) c[ni][q] = 0.f;
#pragma unroll
        for (int ks = 0; ks < 4; ks++) {
            uint32_t bk[8][2];
#pragma unroll
            for (int p = 0; p < 4; p++) {
                uint32_t r[4];
                const int j = (2 * p + k_nt) * 8 + k_j;
                ldm_x4(r, kb + (j * KTS + ks * 16 + k_kh * 8) * 2);
                bk[2 * p][0] = r[0]; bk[2 * p][1] = r[1];
                bk[2 * p + 1][0] = r[2]; bk[2 * p + 1][1] = r[3];
            }
#pragma unroll
            for (int ni = 0; ni < 8; ni++)
                mma_bf16(c[ni], aq[ks], bk[ni]);
        }

        // ---- online softmax (rows g and g+8 of this warp's 16) ----
        float mx_lo = -1e30f, mx_hi = -1e30f;
#pragma unroll
        for (int ni = 0; ni < 8; ni++) {
            mx_lo = fmaxf(mx_lo, fmaxf(c[ni][0], c[ni][1]));
            mx_hi = fmaxf(mx_hi, fmaxf(c[ni][2], c[ni][3]));
        }
#pragma unroll
        for (int off = 1; off < 4; off <<= 1) {
            mx_lo = fmaxf(mx_lo, __shfl_xor_sync(0xffffffffu, mx_lo, off));
            mx_hi = fmaxf(mx_hi, __shfl_xor_sync(0xffffffffu, mx_hi, off));
        }
        const float mn_lo = fmaxf(m_lo, mx_lo);
        const float mn_hi = fmaxf(m_hi, mx_hi);
        const float al_lo = exp2f((m_lo - mn_lo) * EXPC);
        const float al_hi = exp2f((m_hi - mn_hi) * EXPC);
        m_lo = mn_lo; m_hi = mn_hi;
        float s_lo = 0.f, s_hi = 0.f;
#pragma unroll
        for (int ni = 0; ni < 8; ni++) {
            c[ni][0] = exp2f((c[ni][0] - mn_lo) * EXPC);
            c[ni][1] = exp2f((c[ni][1] - mn_lo) * EXPC);
            c[ni][2] = exp2f((c[ni][2] - mn_hi) * EXPC);
            c[ni][3] = exp2f((c[ni][3] - mn_hi) * EXPC);
            s_lo += c[ni][0] + c[ni][1];
            s_hi += c[ni][2] + c[ni][3];
        }
#pragma unroll
        for (int off = 1; off < 4; off <<= 1) {
            s_lo += __shfl_xor_sync(0xffffffffu, s_lo, off);
            s_hi += __shfl_xor_sync(0xffffffffu, s_hi, off);
        }
        l_lo = l_lo * al_lo + s_lo;
        l_hi = l_hi * al_hi + s_hi;
#pragma unroll
        for (int nd = 0; nd < 8; nd++) {
            o[nd][0] *= al_lo; o[nd][1] *= al_lo;
            o[nd][2] *= al_hi; o[nd][3] *= al_hi;
        }

        // ---- O += P @ V ----
#pragma unroll
        for (int ks = 0; ks < 4; ks++) {
            uint32_t pa[4];
            pa[0] = packbf(c[2 * ks][0],     c[2 * ks][1]);
            pa[1] = packbf(c[2 * ks][2],     c[2 * ks][3]);
            pa[2] = packbf(c[2 * ks + 1][0], c[2 * ks + 1][1]);
            pa[3] = packbf(c[2 * ks + 1][2], c[2 * ks + 1][3]);
            uint32_t bv[8][2];
#pragma unroll
            for (int q = 0; q < 4; q++) {
                uint32_t r[4];
                const int j = ks * 16 + v_jh * 8 + v_j;
                const int d = (2 * q + v_dt) * 8;
                ldm_x4_t(r, vb + (j * KTS + d) * 2);
                bv[2 * q][0] = r[0]; bv[2 * q][1] = r[1];
                bv[2 * q + 1][0] = r[2]; bv[2 * q + 1][1] = r[3];
            }
#pragma unroll
            for (int nd = 0; nd < 8; nd++)
                mma_bf16(o[nd], pa, bv[nd]);
        }
        __syncthreads();
    }

    // ---- normalize + write ----
    const float inv_lo = 1.0f / l_lo;
    const float inv_hi = 1.0f / l_hi;
    const int row_lo = qbase + w * 16 + g;
#pragma unroll
    for (int nd = 0; nd < 8; nd++) {
        const int col = h * 64 + nd * 8 + 2 * tg;
        *(uint32_t*)&concat[(size_t)row_lo * ATTN_D + col] =
            packbf(o[nd][0] * inv_lo, o[nd][1] * inv_lo);
        *(uint32_t*)&concat[(size_t)(row_lo + 8) * ATTN_D + col] =
            packbf(o[nd][2] * inv_hi, o[nd][3] * inv_hi);
    }
}

// ---------------- GELU gating (bf16) ----------------
__device__ __forceinline__ float gelu_tanh(float x) {
    const float x3 = x * x * x;
    return 0.5f * x * (1.0f + tanhf(0.7978845608028654f * (x + 0.044715f * x3)));
}

__global__ void __launch_bounds__(256) gelu_kernel(const __nv_bfloat16* __restrict__ proj,
                                                   __nv_bfloat16* __restrict__ gated) {
    const int idx = blockIdx.x * 256 + threadIdx.x;
    const int m  = idx >> 9;
    const int c8 = idx & 511;
    const __nv_bfloat16* base = proj + (size_t)m * NPROJ;
    float f[8], g[8];
    unpack8(*(const uint4*)(base + 3072 + c8 * 8), f);
    unpack8(*(const uint4*)(base + 7168 + c8 * 8), g);
    __nv_bfloat162 o[4];
#pragma unroll
    for (int j = 0; j < 4; j++)
        o[j] = __float22bfloat162_rn(make_float2(f[2 * j] * gelu_tanh(g[2 * j]),
                                                 f[2 * j + 1] * gelu_tanh(g[2 * j + 1])));
    *(uint4*)(gated + (size_t)m * FF_D + c8 * 8) = *(uint4*)o;
}

// ---------------- Launch ----------------
extern "C" void kernel_launch(void* const* d_in, const int* in_sizes, int n_in,
                              void* d_out, int out_size) {
    const float* x      = (const float*)d_in[0];
    const float* lnw    = (const float*)d_in[1];
    const float* lnb    = (const float*)d_in[2];
    const float* w_in   = (const float*)d_in[3];
    const float* w_attn = (const float*)d_in[4];
    const float* w_ff   = (const float*)d_in[5];
    float* out = (float*)d_out;

    __nv_bfloat16 *units, *proj, *concat, *gated, *wT_in, *wT_out;
    cudaGetSymbolAddress((void**)&units,  g_units);
    cudaGetSymbolAddress((void**)&proj,   g_proj);
    cudaGetSymbolAddress((void**)&concat, g_concat);
    cudaGetSymbolAddress((void**)&gated,  g_gated);
    cudaGetSymbolAddress((void**)&wT_in,  g_wT_in);
    cudaGetSymbolAddress((void**)&wT_out, g_wT_out);

    cudaFuncSetAttribute(attn_kernel, cudaFuncAttributeMaxDynamicSharedMemorySize, ASMEM_TOT);
    cudaFuncSetAttribute(gemm_bf16<true>,  cudaFuncAttributeMaxDynamicSharedMemorySize, GSMEM_TOT);
    cudaFuncSetAttribute(gemm_bf16<false>, cudaFuncAttributeMaxDynamicSharedMemorySize, GSMEM_TOT);

    // 0) weight prep (bf16 transposes)
    transpose_to_bf16<<<dim3(NPROJ / 32, MODEL_D / 32), dim3(32, 8)>>>(
        w_in, wT_in, MODEL_D, NPROJ, MODEL_D, 0);
    transpose_to_bf16<<<dim3(MODEL_D / 32, ATTN_D / 32), dim3(32, 8)>>>(
        w_attn, wT_out, ATTN_D, MODEL_D, KOUT, 0);
    transpose_to_bf16<<<dim3(MODEL_D / 32, FF_D / 32), dim3(32, 8)>>>(
        w_ff, wT_out, FF_D, MODEL_D, KOUT, 1024);

    // 1) LayerNorm -> bf16
    ln_kernel<<<ROWS_TOT, 256>>>(x, lnw, lnb, units);

    // 2) proj = units @ w_in  (bf16 out)
    gemm_bf16<true><<<dim3(NPROJ / 128, ROWS_TOT / 128), 256, GSMEM_TOT>>>(
        units, units, 32, MODEL_D, MODEL_D, wT_in, MODEL_D,
        proj, NPROJ, nullptr, 32);

    // 3) attention -> concat (bf16)
    attn_kernel<<<dim3(16, 16, 2), 256, ASMEM_TOT>>>(proj, concat);

    // 4) gelu gating -> gated (bf16)
    gelu_kernel<<<(ROWS_TOT * FF_D / 8) / 256, 256>>>(proj, gated);

    // 5) out = x + concat @ w_attn + gated @ w_ff  (fused K=5120)
    gemm_bf16<false><<<dim3(MODEL_D / 128, ROWS_TOT / 128), 256, GSMEM_TOT>>>(
        concat, gated, 32, ATTN_D, FF_D, wT_out, KOUT,
        out, MODEL_D, x, 160);
}